// round 6
// baseline (speedup 1.0000x reference)
#include <cuda_runtime.h>

// CTC loss forward. One CTA (256 thr) per batch element.
// Phase 1: all 8 warps compute log2-softmax lp values for 32 time steps each
//          (warp w -> t in [32w, 32w+32)) into smem: lpl[t][l] = lp at label
//          lab[l], lpb[t] = lp at blank. Massively parallel, DRAM-bound.
// Phase 2 (after one __syncthreads): warp 0 runs the 256-step alpha DP from
//          smem. Lane l owns states 2l+1 (label) and 2l+2 (blank); state 0 is
//          a replicated scalar. Other warps exit; cross-CTA overlap hides the
//          serial chain. All math in log2 domain.

#define TN 256
#define CN 128
#define LN 32
#define PADV 127
#define NEGF (-1e30f)
#define LOG2E 1.4426950408889634f
#define NLN2 0.6931471805599453f

__device__ __forceinline__ float ex2(float x) {
    float r; asm("ex2.approx.f32 %0, %1;" : "=f"(r) : "f"(x)); return r;
}
__device__ __forceinline__ float lg2(float x) {
    float r; asm("lg2.approx.f32 %0, %1;" : "=f"(r) : "f"(x)); return r;
}
__device__ __forceinline__ float lae2(float a, float b) {      // log2-add-exp2
    return fmaxf(a, b) + lg2(1.0f + ex2(-fabsf(a - b)));
}
__device__ __forceinline__ float lae3(float a, float b, float c) {
    float m = fmaxf(a, fmaxf(b, c));
    return m + lg2(ex2(a - m) + ex2(b - m) + ex2(c - m));
}

__global__ __launch_bounds__(256) void ctc_fused_kernel(
    const int* __restrict__ yt, const float* __restrict__ yp,
    float* __restrict__ out)
{
    const unsigned FULL = 0xffffffffu;
    __shared__ float s_lpl[TN][LN];   // 32 KB: lp at lab[l], log2 domain
    __shared__ float s_lpb[TN];       // 1 KB : lp at blank

    const int tid = threadIdx.x;
    const int w = tid >> 5;
    const int l = tid & 31;
    const int b = blockIdx.x;
    const float* __restrict__ rowf = yp + (size_t)b * TN * CN;
    const float4* __restrict__ row4 = (const float4*)rowf;

    const int lab = yt[b * LN + l];

    // ---------------- phase 1: log-softmax producers (all 8 warps) --------
    #pragma unroll
    for (int i0 = 0; i0 < 32; i0 += 4) {
        float4 v[4];
        #pragma unroll
        for (int j = 0; j < 4; ++j)
            v[j] = row4[(w * 32 + i0 + j) * 32 + l];   // MLP=4 front loads
        #pragma unroll
        for (int j = 0; j < 4; ++j) {
            const int t = w * 32 + i0 + j;
            const float x0 = v[j].x * LOG2E, x1 = v[j].y * LOG2E,
                        x2 = v[j].z * LOG2E, x3 = v[j].w * LOG2E;
            float s = ex2(x0) + ex2(x1) + ex2(x2) + ex2(x3);
            #pragma unroll
            for (int o = 16; o; o >>= 1) s += __shfl_xor_sync(FULL, s, o);
            const float logZ = lg2(s);
            // gather logit at this lane's label (L1 hit: line just loaded)
            const float gl = __ldg(rowf + t * CN + lab) * LOG2E;
            s_lpl[t][l] = gl - logZ;
            if (l == 0) s_lpb[t] = x0 - logZ;          // class 0 = blank
        }
    }
    __syncthreads();

    // ---------------- phase 2: alpha DP (warp 0 only) ---------------------
    if (w == 0) {
        const int labp = __shfl_up_sync(FULL, lab, 1);
        const bool skip = (l >= 1) && (lab != labp);
        const unsigned m = __ballot_sync(FULL, lab != PADV);
        const int len = __popc(m);

        // pre-seed so the t=0 update reproduces alpha0 exactly
        float a0 = 0.0f, a_odd = NEGF, a_even = NEGF;

        #pragma unroll 4
        for (int t = 0; t < TN; ++t) {
            const float lpl = s_lpl[t][l];
            const float lpb = s_lpb[t];
            float po = __shfl_up_sync(FULL, a_odd, 1);   // alpha[2l-1]
            float pe = __shfl_up_sync(FULL, a_even, 1);  // alpha[2l]
            po = (l == 0) ? NEGF : po;
            pe = (l == 0) ? a0 : pe;
            const float n_odd  = lpl + lae3(a_odd, pe, skip ? po : NEGF);
            const float n_even = lpb + lae2(a_even, a_odd);
            a0 += lpb;
            a_odd = n_odd; a_even = n_even;
        }

        // loglik ends at states 2*len (even, lane len-1) and 2*len-1 (odd)
        const float ve = __shfl_sync(FULL, a_even, (len - 1) & 31);
        const float vo = __shfl_sync(FULL, a_odd, (len - 1) & 31);
        if (l == 0) {
            const float ll2 = (len >= 1) ? lae2(ve, vo) : a0;
            out[b] = -ll2 * NLN2;
        }
    }
}

extern "C" void kernel_launch(void* const* d_in, const int* in_sizes, int n_in,
                              void* d_out, int out_size) {
    const int* y_true = (const int*)d_in[0];     // [1024, 32] int32
    const float* y_pred = (const float*)d_in[1]; // [1024, 256, 128] float32
    float* out = (float*)d_out;                  // [1024] float32
    const int B = in_sizes[0] / LN;              // 1024
    ctc_fused_kernel<<<B, 256>>>(y_true, y_pred, out);
}

// round 7
// speedup vs baseline: 1.0587x; 1.0587x over previous
#include <cuda_runtime.h>

// CTC loss forward, two-kernel split.
// K1 (lp_kernel): one warp per (b,t) row computes log2-softmax values at the
//     32 label symbols + blank, writes to global scratch. 262144 warps,
//     DRAM-throughput-bound.
// K2 (dp_kernel): one warp per batch element runs the 256-step alpha DP over
//     the precomputed lp values (coalesced, double-buffered loads). The serial
//     chain is only shfl + logaddexp. All math in log2 domain.

#define TN 256
#define CN 128
#define LN 32
#define BN 1024
#define PADV 127
#define NEGF (-1e30f)
#define LOG2E 1.4426950408889634f
#define NLN2 0.6931471805599453f
#define GK 8            // DP steps per load group

__device__ float g_lpl[(size_t)BN * TN * LN];  // 32 MB: lp at lab[b][l], step t
__device__ float g_lpb[(size_t)BN * TN];       // 1 MB : lp at blank, step t

__device__ __forceinline__ float ex2(float x) {
    float r; asm("ex2.approx.f32 %0, %1;" : "=f"(r) : "f"(x)); return r;
}
__device__ __forceinline__ float lg2(float x) {
    float r; asm("lg2.approx.f32 %0, %1;" : "=f"(r) : "f"(x)); return r;
}
__device__ __forceinline__ float lae2(float a, float b) {      // log2-add-exp2
    return fmaxf(a, b) + lg2(1.0f + ex2(-fabsf(a - b)));
}
__device__ __forceinline__ float lae3(float a, float b, float c) {
    float m = fmaxf(a, fmaxf(b, c));
    return m + lg2(ex2(a - m) + ex2(b - m) + ex2(c - m));
}

// ---------------- K1: per-row log-softmax producer -------------------------
__global__ __launch_bounds__(256) void lp_kernel(
    const int* __restrict__ yt, const float* __restrict__ yp)
{
    const unsigned FULL = 0xffffffffu;
    const int gw = (blockIdx.x * 256 + threadIdx.x) >> 5;  // row index b*TN+t
    const int l = threadIdx.x & 31;
    const int b = gw >> 8;          // TN = 256
    const float* __restrict__ rowf = yp + (size_t)gw * CN;

    const float4 v = ((const float4*)rowf)[l];
    const float x0 = v.x * LOG2E, x1 = v.y * LOG2E,
                x2 = v.z * LOG2E, x3 = v.w * LOG2E;
    float s = ex2(x0) + ex2(x1) + ex2(x2) + ex2(x3);
    #pragma unroll
    for (int o = 16; o; o >>= 1) s += __shfl_xor_sync(FULL, s, o);
    const float logZ = lg2(s);

    const int lab = __ldg(yt + b * LN + l);          // L1/L2 hit (reused 256x)
    const float gl = __ldg(rowf + lab) * LOG2E;      // L1 hit: line just loaded

    g_lpl[(size_t)gw * LN + l] = gl - logZ;
    if (l == 0) g_lpb[gw] = x0 - logZ;               // class 0 = blank
}

// ---------------- K2: alpha DP, one warp per batch element -----------------
__global__ __launch_bounds__(32) void dp_kernel(
    const int* __restrict__ yt, float* __restrict__ out)
{
    const unsigned FULL = 0xffffffffu;
    const int b = blockIdx.x;
    const int l = threadIdx.x;

    const int lab = yt[b * LN + l];
    const int labp = __shfl_up_sync(FULL, lab, 1);
    const bool skip = (l >= 1) && (lab != labp);
    const unsigned m = __ballot_sync(FULL, lab != PADV);
    const int len = __popc(m);

    const float* __restrict__ lpl = g_lpl + (size_t)b * TN * LN;
    const float* __restrict__ lpb = g_lpb + (size_t)b * TN;

    // pre-seed so the t=0 update reproduces alpha0 exactly
    float a0 = 0.0f, a_odd = NEGF, a_even = NEGF;

    float cl[GK], cb[GK];
    #pragma unroll
    for (int i = 0; i < GK; ++i) {
        cl[i] = lpl[i * LN + l];
        cb[i] = lpb[i];
    }

    for (int g = 0; g < TN / GK; ++g) {
        float nl[GK], nb[GK];
        if (g + 1 < TN / GK) {
            #pragma unroll
            for (int i = 0; i < GK; ++i) {
                nl[i] = lpl[((g + 1) * GK + i) * LN + l];
                nb[i] = lpb[(g + 1) * GK + i];
            }
        }
        #pragma unroll
        for (int i = 0; i < GK; ++i) {
            float po = __shfl_up_sync(FULL, a_odd, 1);   // alpha[2l-1]
            float pe = __shfl_up_sync(FULL, a_even, 1);  // alpha[2l]
            po = (l == 0) ? NEGF : po;
            pe = (l == 0) ? a0 : pe;
            const float n_odd  = cl[i] + lae3(a_odd, pe, skip ? po : NEGF);
            const float n_even = cb[i] + lae2(a_even, a_odd);
            a0 += cb[i];
            a_odd = n_odd; a_even = n_even;
        }
        #pragma unroll
        for (int i = 0; i < GK; ++i) { cl[i] = nl[i]; cb[i] = nb[i]; }
    }

    // loglik ends at states 2*len (even, lane len-1) and 2*len-1 (odd)
    const float ve = __shfl_sync(FULL, a_even, (len - 1) & 31);
    const float vo = __shfl_sync(FULL, a_odd, (len - 1) & 31);
    if (l == 0) {
        const float ll2 = (len >= 1) ? lae2(ve, vo) : a0;
        out[b] = -ll2 * NLN2;
    }
}

extern "C" void kernel_launch(void* const* d_in, const int* in_sizes, int n_in,
                              void* d_out, int out_size) {
    const int* y_true = (const int*)d_in[0];     // [1024, 32] int32
    const float* y_pred = (const float*)d_in[1]; // [1024, 256, 128] float32
    float* out = (float*)d_out;                  // [1024] float32
    const int B = in_sizes[0] / LN;              // 1024
    lp_kernel<<<B * TN / 8, 256>>>(y_true, y_pred);   // 8 warps/block
    dp_kernel<<<B, 32>>>(y_true, out);
}